// round 16
// baseline (speedup 1.0000x reference)
#include <cuda_runtime.h>
#include <cstdint>

// Problem constants
#define BATCH 16
#define NA    3
#define NC    20
#define NATTR 25          // 5 + NC
#define IH    52
#define IW    52
#define HW    2704        // IH*IW
#define NBOX  8112        // NA*HW
#define NPAD  8192
#define TOPK  2048
#define NWORDS (TOPK / 64)    // 32 u64 words per suppression row
#define NBLK   (TOPK / 64)    // 32 blocks of 64 candidates
#define MAXE  2048            // edge-list capacity (fallback if exceeded)
#define STRIDE_F 8.0f

typedef unsigned long long u64;

// Accurate libdevice expf (XLA's f32 exp lowering), immune to --use_fast_math.
extern "C" __device__ float __nv_expf(float);

// Scratch (allocation-free: __device__ globals)
__device__ float g_conf[BATCH][NBOX];
__device__ int   g_cls [BATCH][NBOX];
__device__ u64   g_runA[BATCH][NPAD];
__device__ u64   g_runB[BATCH][NPAD];
__device__ int   g_scnt[BATCH][8];              // tournament counters

// NMS staging
__device__ float g_x1[BATCH][TOPK];
__device__ float g_y1[BATCH][TOPK];
__device__ float g_x2[BATCH][TOPK];
__device__ float g_y2[BATCH][TOPK];
__device__ float g_ar[BATCH][TOPK];
__device__ short g_cl[BATCH][TOPK];
__device__ u64   g_vab[BATCH][NWORDS];          // validity bitmask
__device__ u64   g_mask[BATCH][TOPK][NWORDS];   // suppression matrix (sparse-written)
__device__ u64   g_diag[BATCH][TOPK];           // compact diagonal words (coalesced)
__device__ unsigned g_rnz[BATCH][TOPK];         // per-row nonzero-word bitmask

// ---------------------------------------------------------------------------
// Bitwise replica of XLA:GPU's tanh (llvm_ir::EmitFastTanh).
// ---------------------------------------------------------------------------
__device__ __forceinline__ float xla_tanhf(float x) {
    float ax = fabsf(x);
    float xc = fminf(fmaxf(x, -7.90531110763549805f), 7.90531110763549805f);
    float x2 = __fmul_rn(xc, xc);
    float p = -2.76076847742355e-16f;
    p = __fmaf_rn(x2, p, 2.00018790482477e-13f);
    p = __fmaf_rn(x2, p, -8.60467152213735e-11f);
    p = __fmaf_rn(x2, p, 5.12229709037114e-08f);
    p = __fmaf_rn(x2, p, 1.48572235717979e-05f);
    p = __fmaf_rn(x2, p, 6.37261928875436e-04f);
    p = __fmaf_rn(x2, p, 4.89352455891786e-03f);
    p = __fmul_rn(xc, p);
    float q = 1.19825839466702e-06f;
    q = __fmaf_rn(x2, q, 1.18534705686654e-04f);
    q = __fmaf_rn(x2, q, 2.26843463243900e-03f);
    q = __fmaf_rn(x2, q, 4.89352518554385e-03f);
    float r = __fdiv_rn(p, q);
    return (ax < 0.0004f) ? x : r;
}

__device__ __forceinline__ float sigmoid_xla(float x) {
    float t = xla_tanhf(__fmul_rn(0.5f, x));
    return __fmaf_rn(0.5f, t, 0.5f);
}

// ---------------------------------------------------------------------------
// Kernel 1: decode (verbatim R15). CTA 0 zeroes tournament counters.
// ---------------------------------------------------------------------------
__global__ void decode_kernel(const float* __restrict__ in,
                              const float* __restrict__ anchors,
                              float* __restrict__ out) {
    __shared__ float s_out[256 * NATTR];

    if (blockIdx.x == 0 && threadIdx.x < BATCH * 8)
        ((int*)g_scnt)[threadIdx.x] = 0;

    int t = blockIdx.x * 256 + threadIdx.x;     // grid sized exactly: no tail
    int b = t / NBOX, n = t % NBOX;
    int a = n / HW,   r = n % HW;
    int gy = r / IW,  gx = r % IW;

    const float* base = in + ((size_t)(b * NA + a) * NATTR) * HW + r;
    float t0 = base[0 * HW];
    float t1 = base[1 * HW];
    float t2 = base[2 * HW];
    float t3 = base[3 * HW];
    float t4 = base[4 * HW];

    float aw = __fdiv_rn(anchors[a * 2 + 0], STRIDE_F);
    float ah = __fdiv_rn(anchors[a * 2 + 1], STRIDE_F);

    float sx = sigmoid_xla(t0);
    float sy = sigmoid_xla(t1);
    float bx = __fmul_rn(__fadd_rn(sx, (float)gx), STRIDE_F);
    float by = __fmul_rn(__fadd_rn(sy, (float)gy), STRIDE_F);
    float bw = __fmul_rn(__fmul_rn(__nv_expf(t2), aw), STRIDE_F);
    float bh = __fmul_rn(__fmul_rn(__nv_expf(t3), ah), STRIDE_F);
    float conf = sigmoid_xla(t4);

    float* so = s_out + threadIdx.x * NATTR;
    so[0] = bx; so[1] = by; so[2] = bw; so[3] = bh; so[4] = conf;

    float bestv = -3.402823466e+38f;
    int best = 0;
#pragma unroll
    for (int c = 0; c < NC; c++) {
        float v = sigmoid_xla(base[(5 + c) * HW]);
        so[5 + c] = v;
        if (v > bestv) { bestv = v; best = c; }
    }
    g_conf[b][n] = conf;
    g_cls[b][n]  = best;
    __syncthreads();

    float* oblk = out + (size_t)blockIdx.x * 256 * NATTR;
    for (int k = threadIdx.x; k < 256 * NATTR; k += 256)
        oblk[k] = s_out[k];
}

// ---------------------------------------------------------------------------
// Top-K machinery (verbatim R15).
// ---------------------------------------------------------------------------
__device__ __forceinline__ u64 cex(u64 a, u64 v, bool lower, bool desc) {
    u64 mx = a > v ? a : v;
    u64 mn = a > v ? v : a;
    return desc ? (lower ? mx : mn) : (lower ? mn : mx);
}

__device__ __forceinline__ void bitonic_merge_2048(u64& r0, u64& r1,
                                                   u64* s, int t, bool dirDesc) {
    {   // j = 1024: in-thread pair, r0 is lower
        bool sw = dirDesc ? (r0 < r1) : (r0 > r1);
        if (sw) { u64 tmp = r0; r0 = r1; r1 = tmp; }
    }
#pragma unroll
    for (int j = 512; j >= 32; j >>= 1) {
        s[t] = r0; s[t + 1024] = r1;
        __syncthreads();
        u64 v0 = s[t ^ j];
        u64 v1 = s[(t ^ j) + 1024];
        bool lower = (t & j) == 0;
        r0 = cex(r0, v0, lower, dirDesc);
        r1 = cex(r1, v1, lower, dirDesc);
        __syncthreads();
    }
#pragma unroll
    for (int j = 16; j >= 1; j >>= 1) {
        u64 v0 = __shfl_xor_sync(0xFFFFFFFFu, r0, j);
        u64 v1 = __shfl_xor_sync(0xFFFFFFFFu, r1, j);
        bool lower = (t & j) == 0;
        r0 = cex(r0, v0, lower, dirDesc);
        r1 = cex(r1, v1, lower, dirDesc);
    }
}

// Fused tournament sort (verbatim R15).
__global__ void sort_fused(const float* __restrict__ out,
                           float* __restrict__ out_topidx) {
    __shared__ u64 s[2048];
    __shared__ int s_go;
    __shared__ unsigned s_vab32[64];
    int c = blockIdx.x, b = blockIdx.y, t = threadIdx.x;

    // ---- phase 1: local sort of run c ----
    {
        int i = c * 1024 + t;
        u64 mine = 0ull;
        if (i < NBOX) {
            unsigned cb = __float_as_uint(g_conf[b][i]);
            mine = ((u64)cb << 32) | (unsigned)(0xFFFFFFFFu - (unsigned)i);
        }
        bool dirDesc = ((__popc(c) & 1) == 0);

        for (int k2 = 2; k2 <= 1024; k2 <<= 1) {
            for (int j = k2 >> 1; j > 0; j >>= 1) {
                bool descb = (((t & k2) == 0) == dirDesc);
                bool lower = (t & j) == 0;
                if (j >= 32) {
                    s[t] = mine;
                    __syncthreads();
                    u64 v = s[t ^ j];
                    mine = cex(mine, v, lower, descb);
                    __syncthreads();
                } else {
                    u64 v = __shfl_xor_sync(0xFFFFFFFFu, mine, j);
                    mine = cex(mine, v, lower, descb);
                }
            }
        }
        g_runA[b][c * 1024 + t] = mine;
    }
    __threadfence();
    __syncthreads();

    // ---- continuation 1: pair merge ----
    int pc = c >> 1;
    if (t == 0) s_go = atomicAdd(&g_scnt[b][pc], 1);
    __syncthreads();
    if (s_go == 0) return;
    __threadfence();
    {
        const u64* A  = g_runA[b] + 2 * pc * 1024;
        const u64* Bp = A + 1024;
        bool dirDesc = ((__popc(pc) & 1) == 0);
        u64 r0 = A[t];
        u64 r1 = Bp[t];
        bitonic_merge_2048(r0, r1, s, t, dirDesc);
        g_runB[b][pc * 2048 + t]        = r0;
        g_runB[b][pc * 2048 + 1024 + t] = r1;
    }
    __threadfence();
    __syncthreads();

    // ---- continuation 2: quad truncating merge ----
    int qc = pc >> 1;
    if (t == 0) s_go = atomicAdd(&g_scnt[b][4 + qc], 1);
    __syncthreads();
    if (s_go == 0) return;
    __threadfence();
    {
        const u64* A  = g_runB[b] + 2 * qc * 2048;
        const u64* Bp = A + 2048;
        bool dirDesc = ((__popc(qc) & 1) == 0);
        u64 a0 = A[t],        b0 = Bp[t];
        u64 a1 = A[t + 1024], b1 = Bp[t + 1024];
        u64 r0 = a0 > b0 ? a0 : b0;    // bitonic split: top half
        u64 r1 = a1 > b1 ? a1 : b1;
        bitonic_merge_2048(r0, r1, s, t, dirDesc);
        g_runA[b][qc * 2048 + t]        = r0;
        g_runA[b][qc * 2048 + 1024 + t] = r1;
    }
    __threadfence();
    __syncthreads();

    // ---- continuation 3: final truncating merge + prep ----
    if (t == 0) s_go = atomicAdd(&g_scnt[b][6], 1);
    __syncthreads();
    if (s_go == 0) return;
    __threadfence();

    if (t < 64) s_vab32[t] = 0u;
    u64 fr0, fr1;
    {
        const u64* A  = g_runA[b];
        const u64* Bp = A + 2048;
        u64 a0 = A[t],        b0 = Bp[t];
        u64 a1 = A[t + 1024], b1 = Bp[t + 1024];
        fr0 = a0 > b0 ? a0 : b0;
        fr1 = a1 > b1 ? a1 : b1;
        bitonic_merge_2048(fr0, fr1, s, t, true);
    }

#pragma unroll
    for (int q = 0; q < 2; q++) {
        int i = t + q * 1024;
        u64 kk = q ? fr1 : fr0;
        int n = (int)(0xFFFFFFFFu - (unsigned)(kk & 0xFFFFFFFFull));
        out_topidx[b * TOPK + i] = (float)n;
        g_rnz[b][i] = 0u;

        const float* o = out + ((size_t)b * NBOX + n) * NATTR;
        float cx = o[0], cy = o[1], w = o[2], h = o[3];
        float conf = __uint_as_float((unsigned)(kk >> 32));
        float hw2 = __fmul_rn(w, 0.5f);
        float hh2 = __fmul_rn(h, 0.5f);
        float x1 = __fsub_rn(cx, hw2);
        float y1 = __fsub_rn(cy, hh2);
        float x2 = __fadd_rn(cx, hw2);
        float y2 = __fadd_rn(cy, hh2);
        g_x1[b][i] = x1; g_y1[b][i] = y1; g_x2[b][i] = x2; g_y2[b][i] = y2;
        g_ar[b][i] = __fmul_rn(__fadd_rn(__fsub_rn(x2, x1), 1.0f),
                               __fadd_rn(__fsub_rn(y2, y1), 1.0f));
        g_cl[b][i] = (short)g_cls[b][n];
        if (conf >= 0.5f)
            atomicOr(&s_vab32[i >> 5], 1u << (i & 31));
    }
    __syncthreads();
    if (t < 64) ((unsigned*)g_vab[b])[t] = s_vab32[t];
}

// ---------------------------------------------------------------------------
// Kernel 3: suppression mask (R15 sparse version); diagonal now stored to the
// compact g_diag array (coalesced consumer reads).
// ---------------------------------------------------------------------------
__global__ void nms_mask(void) {
    int jb = blockIdx.x, ib = blockIdx.y, b = blockIdx.z;
    if (jb < ib) return;

    __shared__ float jx1[64], jy1[64], jx2[64], jy2[64], jar[64];
    __shared__ u64 s_cm[NC];

    int t = threadIdx.x;
    int j0 = jb * 64;
    if (t < NC) s_cm[t] = 0ull;
    __syncthreads();
    jx1[t] = g_x1[b][j0 + t];
    jy1[t] = g_y1[b][j0 + t];
    jx2[t] = g_x2[b][j0 + t];
    jy2[t] = g_y2[b][j0 + t];
    jar[t] = g_ar[b][j0 + t];
    atomicOr(&s_cm[g_cl[b][j0 + t]], 1ull << t);
    __syncthreads();

    int i = ib * 64 + t;
    float xi1 = g_x1[b][i], yi1 = g_y1[b][i];
    float xi2 = g_x2[b][i], yi2 = g_y2[b][i];
    float ai  = g_ar[b][i];
    short ci  = g_cl[b][i];

    u64 mm = s_cm[ci];
    if (jb == ib) mm = (t < 63) ? (mm & (~0ull << (t + 1))) : 0ull;

    u64 bits = 0ull;
    while (mm) {
        int jj = __ffsll((long long)mm) - 1;
        mm &= mm - 1;
        float ix1 = fmaxf(xi1, jx1[jj]);
        float iy1 = fmaxf(yi1, jy1[jj]);
        float ix2 = fminf(xi2, jx2[jj]);
        float iy2 = fminf(yi2, jy2[jj]);
        float iw = __fadd_rn(__fsub_rn(ix2, ix1), 1.0f); iw = fmaxf(iw, 0.0f);
        float ih = __fadd_rn(__fsub_rn(iy2, iy1), 1.0f); ih = fmaxf(ih, 0.0f);
        float inter = __fmul_rn(iw, ih);
        float den = __fadd_rn(__fsub_rn(__fadd_rn(ai, jar[jj]), inter), 1e-16f);
        float iou = __fdiv_rn(inter, den);
        if (iou >= 0.4f) bits |= 1ull << jj;
    }
    if (jb == ib) {
        g_diag[b][i] = bits;                // compact, coalesced diagonal
    } else if (bits) {
        g_mask[b][i][jb] = bits;
        atomicOr(&g_rnz[b][i], 1u << jb);
    }
}

// ---------------------------------------------------------------------------
// Kernel 4: edge-list greedy reduce with WAVEFRONT Phase B. depmask[w] =
// sender-block bitmask; each round, ALL words whose senders are resolved
// resolve in parallel (snapshot of done-mask keeps rounds deterministic and
// the result identical to the serial order). Senders are strictly lower
// blocks -> acyclic -> terminates; typically 2-4 rounds.
// ---------------------------------------------------------------------------
__global__ void nms_reduce(float* __restrict__ keep_out) {
    __shared__ u64 diagAll[NBLK][64];       // 16 KB
    __shared__ unsigned s_rnz[TOPK];        // 8 KB
    __shared__ u64 edge_val[MAXE];          // 16 KB
    __shared__ short edge_row[MAXE];        // 4 KB
    __shared__ int cnt[NWORDS], basei[NWORDS], fill[NWORDS];
    __shared__ unsigned depmask[NWORDS];
    __shared__ u64 s_vab[NWORDS], keepA[NBLK], s_act[NBLK], s_offnz[NBLK];
    __shared__ unsigned s_done;
    __shared__ int s_total;

    int b = blockIdx.x, t = threadIdx.x;    // 256 threads
    if (t < NWORDS) {
        s_vab[t] = g_vab[b][t];
        cnt[t] = 0; fill[t] = 0; depmask[t] = 0u;
        s_act[t] = 0ull; s_offnz[t] = 0ull;
    }
    if (t == 0) s_done = 0u;
    __syncthreads();

    // preload diagonals (coalesced via g_diag) + rnz; count edges per word
    for (int k = t; k < TOPK; k += 256) {
        int bk = k >> 6, u = k & 63;
        u64 d = g_diag[b][k];
        diagAll[bk][u] = d;
        if (d) atomicOr(&s_act[bk], 1ull << u);
        unsigned rz = g_rnz[b][k];
        s_rnz[k] = rz;
        if (rz) atomicOr(&s_offnz[bk], 1ull << u);
        while (rz) { int w = __ffs(rz) - 1; rz &= rz - 1; atomicAdd(&cnt[w], 1); }
    }
    __syncthreads();

    if (t == 0) {
        int acc = 0;
        for (int w = 0; w < NWORDS; w++) { basei[w] = acc; acc += cnt[w]; }
        s_total = acc;
    }
    __syncthreads();
    int total = s_total;

    if (total <= MAXE) {
        // gather edge words in parallel; build per-word sender-block depmask
        for (int k = t; k < TOPK; k += 256) {
            unsigned rz = s_rnz[k];
            while (rz) {
                int w = __ffs(rz) - 1; rz &= rz - 1;
                int p = basei[w] + atomicAdd(&fill[w], 1);
                edge_row[p] = (short)k;
                edge_val[p] = g_mask[b][k][w];
                atomicOr(&depmask[w], 1u << (k >> 6));
            }
        }
        __syncthreads();

        // Phase A: parallel resolve of blocks with NO incoming edges (rem=0)
        if (t < NWORDS && cnt[t] == 0) {
            u64 cand = s_vab[t];
            u64 act = cand & s_act[t];
            while (act) {
                int u = __ffsll((long long)act) - 1;
                u64 d = diagAll[t][u];
                act &= ~(1ull << u);
                cand &= ~d;
                act &= ~d;
            }
            keepA[t] = cand;
            atomicOr(&s_done, 1u << t);
        }
        __syncthreads();

        // Phase B: wavefront rounds. A word resolves when all sender blocks
        // (strictly lower-numbered) are done; snapshot makes rounds exact.
        for (int round = 0; round < NBLK; round++) {
            unsigned snap = s_done;
            __syncthreads();                // all reads of snap before updates
            if (snap == 0xFFFFFFFFu) break; // uniform across CTA
            if (t < NWORDS && !((snap >> t) & 1u) &&
                (depmask[t] & ~snap) == 0u) {
                u64 rem = 0ull;
                int e0 = basei[t], e1 = e0 + cnt[t];
                for (int e = e0; e < e1; e++) {
                    int r = edge_row[e];
                    if ((keepA[r >> 6] >> (r & 63)) & 1ull)
                        rem |= edge_val[e];
                }
                u64 cand = s_vab[t] & ~rem;
                u64 act = cand & s_act[t];
                while (act) {
                    int u = __ffsll((long long)act) - 1;
                    u64 d = diagAll[t][u];
                    act &= ~(1ull << u);
                    cand &= ~d;
                    act &= ~d;
                }
                keepA[t] = cand;
                atomicOr(&s_done, 1u << t);
            }
            __syncthreads();                // publish keepA + s_done
        }
        __syncthreads();
    } else {
        // Fallback: serial loop (verbatim R12 semantics)
        __shared__ u64 s_rem[NWORDS];
        __shared__ u64 s_keep;
        if (t < NWORDS) s_rem[t] = 0ull;
        __syncthreads();
        for (int bk = 0; bk < NBLK; bk++) {
            if (t == 0) {
                u64 cand = s_vab[bk] & ~s_rem[bk];
                u64 act = cand & s_act[bk];
                while (act) {
                    int u = __ffsll((long long)act) - 1;
                    u64 d = diagAll[bk][u];
                    act &= ~(1ull << u);
                    cand &= ~d;
                    act &= ~d;
                }
                s_keep = cand;
            }
            __syncthreads();
            u64 k64 = s_keep;
            if (t == 0) keepA[bk] = k64;
            if (t < NWORDS) {
                int w = t;
                u64 ka = k64 & s_offnz[bk];
                if (w > bk && ka) {
                    u64 part = 0ull;
                    while (ka) {
                        int u = __ffsll((long long)ka) - 1;
                        ka &= ka - 1;
                        int row = bk * 64 + u;
                        if ((s_rnz[row] >> w) & 1u)
                            part |= g_mask[b][row][w];
                    }
                    if (part) atomicOr(&s_rem[w], part);
                }
            }
            __syncthreads();
        }
    }

    // write keep
    for (int k = t; k < TOPK; k += 256)
        keep_out[b * TOPK + k] =
            ((keepA[k >> 6] >> (k & 63)) & 1ull) ? 1.0f : 0.0f;
}

// ---------------------------------------------------------------------------
// Launch: out = [output(B*NBOX*NATTR) | top_idx(B*TOPK) | keep(B*TOPK)] float32
// ---------------------------------------------------------------------------
extern "C" void kernel_launch(void* const* d_in, const int* in_sizes, int n_in,
                              void* d_out, int out_size) {
    (void)in_sizes; (void)n_in; (void)out_size;
    const float* in      = (const float*)d_in[0];
    const float* anchors = (const float*)d_in[1];
    float* out      = (float*)d_out;
    float* top_out  = out + (size_t)BATCH * NBOX * NATTR;
    float* keep_out = top_out + (size_t)BATCH * TOPK;

    int total = BATCH * NBOX;                 // 129792 = 256 * 507, no tail
    decode_kernel<<<total / 256, 256>>>(in, anchors, out);

    sort_fused<<<dim3(8, BATCH), 1024>>>(out, top_out);

    nms_mask<<<dim3(TOPK / 64, TOPK / 64, BATCH), 64>>>();
    nms_reduce<<<BATCH, 256>>>(keep_out);
}